// round 4
// baseline (speedup 1.0000x reference)
#include <cuda_runtime.h>

#define BATCH 4
#define HEADS 6
#define NG 24
#define NS 1024
#define DH 64
#define CD 384
#define NN (NS*NS)
#define KTOP 734003
#define CAP 1048576

#define OFF_PROJ 0
#define OFF_MAP  1572864
#define OFF_CAUS 1576960
#define OFF_NONC 26742784
#define OFF_MASK 51908608

// ---- scratch ----
__device__ float g_q[NG*NS*DH];       // [g][n][d]
__device__ float g_k[NG*DH*NS];       // [g][d][m]
__device__ float g_v[NG*NS*DH];       // [g][m][d]
__device__ float g_o[BATCH*CD*NS];    // AV partial (m half 0)
__device__ float g_oB[BATCH*CD*NS];   // AV partial (m half 1)
__device__ unsigned long long g_cand[(size_t)NG*CAP];
__device__ unsigned int       g_cnt[NG];
__device__ unsigned int       g_hist[NG*8192];
__device__ unsigned long long g_prefix[NG];
__device__ unsigned int       g_krem[NG];

// ---------------------------------------------------------------------------
__global__ void init_kernel(float* out) {
    int t = blockIdx.x * blockDim.x + threadIdx.x;
    if (t < NG*8192) g_hist[t] = 0u;
    if (t < BATCH*NS) out[OFF_MAP + t] = 0.f;
    if (t < NG) { g_prefix[t] = 0ull; g_krem[t] = (unsigned)KTOP; g_cnt[t] = 0u; }
}

// ---------------------------------------------------------------------------
// QKV projections: 128(o) x 128(n) tiles, 8x8 per thread.
__global__ void __launch_bounds__(256) proj_kernel(
        const float* __restrict__ qin, const float* __restrict__ cin,
        const float* __restrict__ Wq, const float* __restrict__ Wk,
        const float* __restrict__ Wv) {
    __shared__ float ws[16][128];
    __shared__ float xs[16][128];
    int which = blockIdx.z;
    int b = blockIdx.y;
    int otile = (blockIdx.x >> 3) * 128;
    int ntile = (blockIdx.x & 7) * 128;
    const float* W = (which == 0) ? Wq : (which == 1 ? Wk : Wv);
    const float* X = ((which == 0) ? qin : cin) + (size_t)b * CD * NS;
    int t = threadIdx.x;
    int tx = t & 15, ty = t >> 4;
    float acc[8][8];
    #pragma unroll
    for (int i = 0; i < 8; i++)
        #pragma unroll
        for (int j = 0; j < 8; j++) acc[i][j] = 0.f;

    for (int c0 = 0; c0 < CD; c0 += 16) {
        #pragma unroll
        for (int i = 0; i < 2; i++) {           // W transpose -> ws[c][o]
            int o = t & 127;
            int cg = (t >> 7) + i * 2;
            float4 w4 = *(const float4*)&W[(size_t)(otile + o) * CD + c0 + cg * 4];
            ws[cg*4+0][o] = w4.x; ws[cg*4+1][o] = w4.y;
            ws[cg*4+2][o] = w4.z; ws[cg*4+3][o] = w4.w;
        }
        #pragma unroll
        for (int i = 0; i < 2; i++) {           // xs[c][n]
            int idx = t + i * 256;
            int c = idx >> 5, ng = idx & 31;
            *(float4*)&xs[c][ng*4] = *(const float4*)&X[(size_t)(c0 + c) * NS + ntile + ng*4];
        }
        __syncthreads();
        #pragma unroll
        for (int k = 0; k < 16; k++) {
            float rw[8], rx[8];
            *(float4*)&rw[0] = *(const float4*)&ws[k][ty*8];
            *(float4*)&rw[4] = *(const float4*)&ws[k][ty*8+4];
            *(float4*)&rx[0] = *(const float4*)&xs[k][tx*8];
            *(float4*)&rx[4] = *(const float4*)&xs[k][tx*8+4];
            #pragma unroll
            for (int i = 0; i < 8; i++)
                #pragma unroll
                for (int j = 0; j < 8; j++)
                    acc[i][j] = fmaf(rw[i], rx[j], acc[i][j]);
        }
        __syncthreads();
    }
    int h = (otile + ty * 8) >> 6;              // 8 consecutive o stay in one head
    int d0 = (otile + ty * 8) & 63;
    int g = b * HEADS + h;
    if (which == 1) {
        #pragma unroll
        for (int r = 0; r < 8; r++) {
            size_t base = ((size_t)g * DH + d0 + r) * NS + ntile + tx * 8;
            *(float4*)&g_k[base]   = make_float4(acc[r][0], acc[r][1], acc[r][2], acc[r][3]);
            *(float4*)&g_k[base+4] = make_float4(acc[r][4], acc[r][5], acc[r][6], acc[r][7]);
        }
    } else {
        float* dst = (which == 0) ? g_q : g_v;
        #pragma unroll
        for (int c = 0; c < 8; c++) {
            int n = ntile + tx * 8 + c;
            size_t base = ((size_t)g * NS + n) * DH + d0;
            *(float4*)&dst[base]   = make_float4(acc[0][c], acc[1][c], acc[2][c], acc[3][c]);
            *(float4*)&dst[base+4] = make_float4(acc[4][c], acc[5][c], acc[6][c], acc[7][c]);
        }
    }
}

// ---------------------------------------------------------------------------
__device__ __forceinline__ void hist_add(unsigned* hist, unsigned bin) {
    unsigned m = __match_any_sync(0xffffffffu, bin);
    if ((int)(threadIdx.x & 31) == __ffs(m) - 1) atomicAdd(&hist[bin], __popc(m));
}

// scores + softmax + pass-1 histogram. 512 threads, 32 rows x 1024 cols.
__global__ void __launch_bounds__(512, 1) attn_kernel(float* __restrict__ attn) {
    extern __shared__ float sm[];
    float* qs = sm;                        // [64][36] transposed q
    float* ks = sm + 64*36;                // [8][1024]
    float* red = ks + 8*1024;              // [16][8]
    unsigned* hist = (unsigned*)(red + 128);
    int g = blockIdx.y;
    int n0 = blockIdx.x * 32;
    int t = threadIdx.x;
    int tx = t & 127, ty = t >> 7;
    int lane = t & 31, wid = t >> 5;

    for (int i = t; i < 8192; i += 512) hist[i] = 0u;
    {   // load q transposed
        int n = t >> 4, dg = t & 15;
        float4 q4 = *(const float4*)&g_q[((size_t)g * NS + n0 + n) * DH + dg * 4];
        qs[(dg*4+0)*36 + n] = q4.x; qs[(dg*4+1)*36 + n] = q4.y;
        qs[(dg*4+2)*36 + n] = q4.z; qs[(dg*4+3)*36 + n] = q4.w;
    }
    float acc[8][8];
    #pragma unroll
    for (int i = 0; i < 8; i++)
        #pragma unroll
        for (int j = 0; j < 8; j++) acc[i][j] = 0.f;

    for (int dc = 0; dc < 8; dc++) {
        __syncthreads();
        #pragma unroll
        for (int i = 0; i < 4; i++) {
            int idx = t + i * 512;
            int dd = idx >> 8, mg = idx & 255;
            *(float4*)&ks[dd*1024 + mg*4] =
                *(const float4*)&g_k[((size_t)g * DH + dc*8 + dd) * NS + mg*4];
        }
        __syncthreads();
        #pragma unroll
        for (int dd = 0; dd < 8; dd++) {
            int d = dc * 8 + dd;
            float rq[8], ck[8];
            *(float4*)&rq[0] = *(const float4*)&qs[d*36 + ty*8];
            *(float4*)&rq[4] = *(const float4*)&qs[d*36 + ty*8 + 4];
            *(float4*)&ck[0] = *(const float4*)&ks[dd*1024 + tx*8];
            *(float4*)&ck[4] = *(const float4*)&ks[dd*1024 + tx*8 + 4];
            #pragma unroll
            for (int i = 0; i < 8; i++)
                #pragma unroll
                for (int j = 0; j < 8; j++)
                    acc[i][j] = fmaf(rq[i], ck[j], acc[i][j]);
        }
    }
    // scale + row max (row = n0 + ty*8 + i, owned by 4 warps sharing ty)
    float rmax[8];
    #pragma unroll
    for (int i = 0; i < 8; i++) {
        float m = -1e30f;
        #pragma unroll
        for (int j = 0; j < 8; j++) { acc[i][j] *= 0.125f; m = fmaxf(m, acc[i][j]); }
        #pragma unroll
        for (int off = 16; off >= 1; off >>= 1)
            m = fmaxf(m, __shfl_xor_sync(0xffffffffu, m, off));
        rmax[i] = m;
    }
    __syncthreads();
    if (lane == 0) {
        #pragma unroll
        for (int i = 0; i < 8; i++) red[wid*8 + i] = rmax[i];
    }
    __syncthreads();
    #pragma unroll
    for (int i = 0; i < 8; i++) {
        float m = red[(ty*4)*8 + i];
        m = fmaxf(m, red[(ty*4+1)*8 + i]);
        m = fmaxf(m, red[(ty*4+2)*8 + i]);
        m = fmaxf(m, red[(ty*4+3)*8 + i]);
        rmax[i] = m;
    }
    float rsum[8];
    #pragma unroll
    for (int i = 0; i < 8; i++) {
        float s = 0.f;
        #pragma unroll
        for (int j = 0; j < 8; j++) { acc[i][j] = expf(acc[i][j] - rmax[i]); s += acc[i][j]; }
        #pragma unroll
        for (int off = 16; off >= 1; off >>= 1)
            s += __shfl_xor_sync(0xffffffffu, s, off);
        rsum[i] = s;
    }
    __syncthreads();
    if (lane == 0) {
        #pragma unroll
        for (int i = 0; i < 8; i++) red[wid*8 + i] = rsum[i];
    }
    __syncthreads();
    #pragma unroll
    for (int i = 0; i < 8; i++) {
        float s = red[(ty*4)*8+i] + red[(ty*4+1)*8+i] + red[(ty*4+2)*8+i] + red[(ty*4+3)*8+i];
        rsum[i] = 1.0f / s;
    }
    // write + histogram
    size_t gb = (size_t)g * NN;
    #pragma unroll
    for (int i = 0; i < 8; i++) {
        size_t base = gb + (size_t)(n0 + ty*8 + i) * NS + tx * 8;
        float p[8];
        #pragma unroll
        for (int j = 0; j < 8; j++) p[j] = acc[i][j] * rsum[i];
        *(float4*)&attn[base]   = make_float4(p[0], p[1], p[2], p[3]);
        *(float4*)&attn[base+4] = make_float4(p[4], p[5], p[6], p[7]);
        #pragma unroll
        for (int j = 0; j < 8; j++)
            hist_add(hist, __float_as_uint(p[j]) >> 19);
    }
    __syncthreads();
    for (int i = t; i < 8192; i += 512)
        if (hist[i]) atomicAdd(&g_hist[g*8192 + i], hist[i]);
}

// ---------------------------------------------------------------------------
// scan: find bin holding the krem-th largest, extend prefix, zero hist.
__global__ void scan_kernel() {
    __shared__ unsigned int ssum[256];
    int g = blockIdx.x;
    int t = threadIdx.x;
    unsigned int* h = &g_hist[g * 8192];
    int hi = 8191 - t * 32;
    unsigned int mysum = 0;
    #pragma unroll
    for (int k = 0; k < 32; k++) mysum += h[hi - k];
    ssum[t] = mysum;
    __syncthreads();
    for (int off = 1; off < 256; off <<= 1) {
        unsigned int v = (t >= off) ? ssum[t - off] : 0u;
        __syncthreads();
        ssum[t] += v;
        __syncthreads();
    }
    unsigned int incl = ssum[t], excl = incl - mysum;
    unsigned int kr = g_krem[g];
    if (excl < kr && kr <= incl) {
        unsigned int cum = excl;
        for (int k = 0; k < 32; k++) {
            int bin = hi - k;
            unsigned int c = h[bin];
            if (cum + c >= kr) {
                g_prefix[g] = (g_prefix[g] << 13) | (unsigned long long)bin;
                g_krem[g] = kr - cum;
                break;
            }
            cum += c;
        }
    }
    __syncthreads();
    for (int i = t; i < 8192; i += 256) h[i] = 0u;
}

// ---------------------------------------------------------------------------
// compact candidates matching pass-1 bin; build pass-2 histogram on the fly.
__global__ void compact_kernel(const float* __restrict__ attn) {
    __shared__ unsigned hist[8192];
    int g = blockIdx.y;
    int t = threadIdx.x;
    int lane = t & 31;
    for (int i = t; i < 8192; i += 256) hist[i] = 0u;
    __syncthreads();
    unsigned long long pref = g_prefix[g];
    size_t gb = (size_t)g * NN;
    int base = blockIdx.x * 65536;
    for (int i = t * 4; i < 65536; i += 1024) {
        float4 v4 = *(const float4*)&attn[gb + base + i];
        float vv[4] = {v4.x, v4.y, v4.z, v4.w};
        #pragma unroll
        for (int c = 0; c < 4; c++) {
            int idx = base + i + c;
            unsigned long long key =
                ((unsigned long long)__float_as_uint(vv[c]) << 20) |
                (unsigned long long)(1048575 - idx);
            bool sel = ((key >> 39) == pref);
            unsigned bm = __ballot_sync(0xffffffffu, sel);
            if (bm) {
                int ldr = __ffs(bm) - 1;
                unsigned pos = 0;
                if (lane == ldr) pos = atomicAdd(&g_cnt[g], (unsigned)__popc(bm));
                pos = __shfl_sync(0xffffffffu, pos, ldr);
                if (sel) {
                    g_cand[(size_t)g * CAP + pos + __popc(bm & ((1u << lane) - 1u))] = key;
                    atomicAdd(&hist[(unsigned)((key >> 26) & 8191)], 1u);
                }
            }
        }
    }
    __syncthreads();
    for (int i = t; i < 8192; i += 256)
        if (hist[i]) atomicAdd(&g_hist[g*8192 + i], hist[i]);
}

// passes 3/4 over the compacted list
__global__ void candpass_kernel(int shift) {
    __shared__ unsigned hist[8192];
    int g = blockIdx.y;
    int t = threadIdx.x;
    for (int i = t; i < 8192; i += 256) hist[i] = 0u;
    __syncthreads();
    unsigned long long pref = g_prefix[g];
    unsigned n = g_cnt[g];
    for (unsigned i = blockIdx.x * 256 + t; i < n; i += 8 * 256) {
        unsigned long long key = g_cand[(size_t)g * CAP + i];
        if ((key >> (shift + 13)) == pref)
            atomicAdd(&hist[(unsigned)((key >> shift) & 8191)], 1u);
    }
    __syncthreads();
    for (int i = t; i < 8192; i += 256)
        if (hist[i]) atomicAdd(&g_hist[g*8192 + i], hist[i]);
}

// ---------------------------------------------------------------------------
// AV: 256(n) x 64(d) x 512(m) per block, 8x8 per thread, m split in halves.
__global__ void __launch_bounds__(256) av_kernel(const float* __restrict__ attn) {
    __shared__ float as[32*256];   // [m][n]
    __shared__ float vs[32*64];    // [m][d]
    int g = blockIdx.y;
    int b = g / HEADS, h = g % HEADS;
    int n0 = (blockIdx.x >> 1) * 256;
    int m0 = (blockIdx.x & 1) * 512;
    int t = threadIdx.x;
    int tx = t & 7, ty = t >> 3;
    float acc[8][8];
    #pragma unroll
    for (int i = 0; i < 8; i++)
        #pragma unroll
        for (int j = 0; j < 8; j++) acc[i][j] = 0.f;

    for (int mc = 0; mc < 16; mc++) {
        int mb = m0 + mc * 32;
        __syncthreads();
        {   // attn transpose tile: thread owns row n = t
            const float* src = attn + (size_t)g * NN + (size_t)(n0 + t) * NS + mb;
            #pragma unroll
            for (int i = 0; i < 8; i++) {
                float4 a4 = *(const float4*)&src[i*4];
                as[(i*4+0)*256 + t] = a4.x; as[(i*4+1)*256 + t] = a4.y;
                as[(i*4+2)*256 + t] = a4.z; as[(i*4+3)*256 + t] = a4.w;
            }
        }
        #pragma unroll
        for (int i = 0; i < 2; i++) {
            int idx = t + i * 256;
            int m = idx >> 4, dg = idx & 15;
            *(float4*)&vs[m*64 + dg*4] =
                *(const float4*)&g_v[((size_t)g * NS + mb + m) * DH + dg*4];
        }
        __syncthreads();
        #pragma unroll
        for (int m = 0; m < 32; m++) {
            float ra[8], rv[8];
            *(float4*)&ra[0] = *(const float4*)&as[m*256 + ty*8];
            *(float4*)&ra[4] = *(const float4*)&as[m*256 + ty*8 + 4];
            *(float4*)&rv[0] = *(const float4*)&vs[m*64 + tx*8];
            *(float4*)&rv[4] = *(const float4*)&vs[m*64 + tx*8 + 4];
            #pragma unroll
            for (int i = 0; i < 8; i++)
                #pragma unroll
                for (int j = 0; j < 8; j++)
                    acc[i][j] = fmaf(ra[i], rv[j], acc[i][j]);
        }
    }
    float* dst = m0 ? g_oB : g_o;
    #pragma unroll
    for (int j = 0; j < 8; j++) {
        size_t base = ((size_t)b * CD + h * DH + tx * 8 + j) * NS + n0 + ty * 8;
        *(float4*)&dst[base]   = make_float4(acc[0][j], acc[1][j], acc[2][j], acc[3][j]);
        *(float4*)&dst[base+4] = make_float4(acc[4][j], acc[5][j], acc[6][j], acc[7][j]);
    }
}

// ---------------------------------------------------------------------------
// out_proj = Wo @ (g_o + g_oB) + bo.  128(o) x 64(n) tiles, 8x4 per thread.
__global__ void __launch_bounds__(256) oproj_kernel(
        const float* __restrict__ Wo, const float* __restrict__ bo,
        float* __restrict__ out) {
    __shared__ float ws[16][128];
    __shared__ float xs[16][64];
    int b = blockIdx.y;
    int otile = (blockIdx.x >> 4) * 128;
    int ntile = (blockIdx.x & 15) * 64;
    int t = threadIdx.x;
    int tx = t & 15, ty = t >> 4;
    float acc[8][4];
    #pragma unroll
    for (int i = 0; i < 8; i++)
        #pragma unroll
        for (int j = 0; j < 4; j++) acc[i][j] = 0.f;

    for (int c0 = 0; c0 < CD; c0 += 16) {
        #pragma unroll
        for (int i = 0; i < 2; i++) {
            int o = t & 127;
            int cg = (t >> 7) + i * 2;
            float4 w4 = *(const float4*)&Wo[(size_t)(otile + o) * CD + c0 + cg * 4];
            ws[cg*4+0][o] = w4.x; ws[cg*4+1][o] = w4.y;
            ws[cg*4+2][o] = w4.z; ws[cg*4+3][o] = w4.w;
        }
        {
            int c = t >> 4, ng = t & 15;
            size_t idx = ((size_t)b * CD + c0 + c) * NS + ntile + ng * 4;
            float4 a = *(const float4*)&g_o[idx];
            float4 bb = *(const float4*)&g_oB[idx];
            xs[c][ng*4+0] = a.x + bb.x; xs[c][ng*4+1] = a.y + bb.y;
            xs[c][ng*4+2] = a.z + bb.z; xs[c][ng*4+3] = a.w + bb.w;
        }
        __syncthreads();
        #pragma unroll
        for (int k = 0; k < 16; k++) {
            float rw[8], rx[4];
            *(float4*)&rw[0] = *(const float4*)&ws[k][ty*8];
            *(float4*)&rw[4] = *(const float4*)&ws[k][ty*8+4];
            *(float4*)&rx[0] = *(const float4*)&xs[k][tx*4];
            #pragma unroll
            for (int i = 0; i < 8; i++)
                #pragma unroll
                for (int j = 0; j < 4; j++)
                    acc[i][j] = fmaf(rw[i], rx[j], acc[i][j]);
        }
        __syncthreads();
    }
    #pragma unroll
    for (int r = 0; r < 8; r++) {
        int o = otile + ty * 8 + r;
        float bias = bo[o];
        *(float4*)&out[((size_t)b * CD + o) * NS + ntile + tx * 4] =
            make_float4(acc[r][0] + bias, acc[r][1] + bias, acc[r][2] + bias, acc[r][3] + bias);
    }
}

// ---------------------------------------------------------------------------
// split into causal / noncausal / mask + attn_map accumulation. float4 IO.
__global__ void mask_kernel(float* __restrict__ out) {
    int g = blockIdx.y;
    int b = g / HEADS;
    unsigned long long thr = g_prefix[g];
    int n0 = blockIdx.x * 16;
    int t = threadIdx.x;
    float* caus = out + OFF_CAUS;
    float* nonc = out + OFF_NONC;
    float* mask = out + OFF_MASK;
    size_t gb = (size_t)g * NN;
    float cs0 = 0.f, cs1 = 0.f, cs2 = 0.f, cs3 = 0.f;
    #pragma unroll 4
    for (int r = 0; r < 16; r++) {
        int idx = (n0 + r) * NS + t * 4;
        float4 v = *(const float4*)&caus[gb + idx];
        float vv[4] = {v.x, v.y, v.z, v.w};
        float cc[4], nc[4], mk[4];
        #pragma unroll
        for (int c = 0; c < 4; c++) {
            unsigned long long key =
                ((unsigned long long)__float_as_uint(vv[c]) << 20) |
                (unsigned long long)(1048575 - (idx + c));
            bool sel = (key >= thr);
            cc[c] = sel ? vv[c] : 0.f;
            nc[c] = sel ? 0.f : vv[c];
            mk[c] = sel ? 1.f : 0.f;
        }
        cs0 += vv[0]; cs1 += vv[1]; cs2 += vv[2]; cs3 += vv[3];
        *(float4*)&caus[gb + idx] = make_float4(cc[0], cc[1], cc[2], cc[3]);
        *(float4*)&nonc[gb + idx] = make_float4(nc[0], nc[1], nc[2], nc[3]);
        *(float4*)&mask[gb + idx] = make_float4(mk[0], mk[1], mk[2], mk[3]);
    }
    const float sc = 1.f / 6144.f;
    atomicAdd(&out[OFF_MAP + b * NS + t*4 + 0], cs0 * sc);
    atomicAdd(&out[OFF_MAP + b * NS + t*4 + 1], cs1 * sc);
    atomicAdd(&out[OFF_MAP + b * NS + t*4 + 2], cs2 * sc);
    atomicAdd(&out[OFF_MAP + b * NS + t*4 + 3], cs3 * sc);
}

// ---------------------------------------------------------------------------
extern "C" void kernel_launch(void* const* d_in, const int* in_sizes, int n_in,
                              void* d_out, int out_size) {
    const float* query   = (const float*)d_in[0];
    const float* context = (const float*)d_in[1];
    const float* Wq      = (const float*)d_in[2];
    const float* Wk      = (const float*)d_in[3];
    const float* Wv      = (const float*)d_in[4];
    const float* Wo      = (const float*)d_in[5];
    const float* bo      = (const float*)d_in[6];
    float* out = (float*)d_out;
    float* attn = out + OFF_CAUS;

    const int ATTN_SMEM = (64*36 + 8*1024 + 128) * 4 + 8192 * 4;
    static int configured = 0;
    if (!configured) {
        cudaFuncSetAttribute(attn_kernel, cudaFuncAttributeMaxDynamicSharedMemorySize, ATTN_SMEM);
        configured = 1;
    }

    init_kernel<<<768, 256>>>(out);
    proj_kernel<<<dim3(24, 4, 3), 256>>>(query, context, Wq, Wk, Wv);
    attn_kernel<<<dim3(32, NG), 512, ATTN_SMEM>>>(attn);
    scan_kernel<<<NG, 256>>>();                 // pass 1
    compact_kernel<<<dim3(16, NG), 256>>>(attn);
    scan_kernel<<<NG, 256>>>();                 // pass 2
    candpass_kernel<<<dim3(8, NG), 256>>>(13);
    scan_kernel<<<NG, 256>>>();                 // pass 3
    candpass_kernel<<<dim3(8, NG), 256>>>(0);
    scan_kernel<<<NG, 256>>>();                 // pass 4
    av_kernel<<<dim3(8, NG), 256>>>(attn);
    oproj_kernel<<<dim3(48, 4), 256>>>(Wo, bo, out);
    mask_kernel<<<dim3(64, NG), 256>>>(out);
}

// round 5
// speedup vs baseline: 1.0111x; 1.0111x over previous
#include <cuda_runtime.h>

#define BATCH 4
#define HEADS 6
#define NG 24
#define NS 1024
#define DH 64
#define CD 384
#define NN (NS*NS)
#define KTOP 734003
#define CAP 1048576

#define OFF_PROJ 0
#define OFF_MAP  1572864
#define OFF_CAUS 1576960
#define OFF_NONC 26742784
#define OFF_MASK 51908608

// ---- scratch ----
__device__ float g_q[NG*NS*DH];       // [g][n][d]
__device__ float g_k[NG*DH*NS];       // [g][d][m]
__device__ float g_v[NG*NS*DH];       // [g][m][d]
__device__ float g_o[BATCH*CD*NS];    // AV partial (m half 0)
__device__ float g_oB[BATCH*CD*NS];   // AV partial (m half 1)
__device__ unsigned long long g_cand[(size_t)NG*CAP];
__device__ unsigned int       g_cnt[NG];
__device__ unsigned int       g_hist[NG*8192];
__device__ unsigned long long g_prefix[NG];
__device__ unsigned int       g_krem[NG];

// ---------------------------------------------------------------------------
// init split into 4 launches so attn_kernel is the 6th launch (ncu -s 5 -c 1).
__global__ void initseg_kernel(float* out, int mode) {
    int t = blockIdx.x * blockDim.x + threadIdx.x;
    if (mode == 0) g_hist[t] = 0u;
    else if (mode == 1) g_hist[98304 + t] = 0u;
    else if (mode == 2) { if (t < BATCH*NS) out[OFF_MAP + t] = 0.f; }
    else { if (t < NG) { g_prefix[t] = 0ull; g_krem[t] = (unsigned)KTOP; g_cnt[t] = 0u; } }
}

// ---------------------------------------------------------------------------
// QKV projections: 128(o) x 128(n) tiles, 8x8 per thread, split n-columns
// (tx*4 and 64+tx*4) for conflict-free LDS.
__global__ void __launch_bounds__(256) proj_kernel(
        const float* __restrict__ qin, const float* __restrict__ cin,
        const float* __restrict__ Wq, const float* __restrict__ Wk,
        const float* __restrict__ Wv) {
    __shared__ float ws[16][128];
    __shared__ float xs[16][128];
    int which = blockIdx.z;
    int b = blockIdx.y;
    int otile = (blockIdx.x >> 3) * 128;
    int ntile = (blockIdx.x & 7) * 128;
    const float* W = (which == 0) ? Wq : (which == 1 ? Wk : Wv);
    const float* X = ((which == 0) ? qin : cin) + (size_t)b * CD * NS;
    int t = threadIdx.x;
    int tx = t & 15, ty = t >> 4;
    float acc[8][8];
    #pragma unroll
    for (int i = 0; i < 8; i++)
        #pragma unroll
        for (int j = 0; j < 8; j++) acc[i][j] = 0.f;

    for (int c0 = 0; c0 < CD; c0 += 16) {
        #pragma unroll
        for (int i = 0; i < 2; i++) {           // W transpose -> ws[c][o]
            int o = t & 127;
            int cg = (t >> 7) + i * 2;
            float4 w4 = *(const float4*)&W[(size_t)(otile + o) * CD + c0 + cg * 4];
            ws[cg*4+0][o] = w4.x; ws[cg*4+1][o] = w4.y;
            ws[cg*4+2][o] = w4.z; ws[cg*4+3][o] = w4.w;
        }
        #pragma unroll
        for (int i = 0; i < 2; i++) {           // xs[c][n]
            int idx = t + i * 256;
            int c = idx >> 5, ng = idx & 31;
            *(float4*)&xs[c][ng*4] = *(const float4*)&X[(size_t)(c0 + c) * NS + ntile + ng*4];
        }
        __syncthreads();
        #pragma unroll
        for (int k = 0; k < 16; k++) {
            float rw[8], rx[8];
            *(float4*)&rw[0] = *(const float4*)&ws[k][ty*8];
            *(float4*)&rw[4] = *(const float4*)&ws[k][ty*8+4];
            *(float4*)&rx[0] = *(const float4*)&xs[k][tx*4];        // cols tx*4..+3
            *(float4*)&rx[4] = *(const float4*)&xs[k][64 + tx*4];   // cols 64+tx*4..+3
            #pragma unroll
            for (int i = 0; i < 8; i++)
                #pragma unroll
                for (int j = 0; j < 8; j++)
                    acc[i][j] = fmaf(rw[i], rx[j], acc[i][j]);
        }
        __syncthreads();
    }
    int h = (otile + ty * 8) >> 6;              // 8 consecutive o stay in one head
    int d0 = (otile + ty * 8) & 63;
    int g = b * HEADS + h;
    if (which == 1) {
        #pragma unroll
        for (int r = 0; r < 8; r++) {
            size_t rowb = ((size_t)g * DH + d0 + r) * NS + ntile;
            *(float4*)&g_k[rowb + tx*4]      = make_float4(acc[r][0], acc[r][1], acc[r][2], acc[r][3]);
            *(float4*)&g_k[rowb + 64 + tx*4] = make_float4(acc[r][4], acc[r][5], acc[r][6], acc[r][7]);
        }
    } else {
        float* dst = (which == 0) ? g_q : g_v;
        #pragma unroll
        for (int c = 0; c < 8; c++) {
            int n = ntile + ((c < 4) ? (tx*4 + c) : (64 + tx*4 + c - 4));
            size_t base = ((size_t)g * NS + n) * DH + d0;
            *(float4*)&dst[base]   = make_float4(acc[0][c], acc[1][c], acc[2][c], acc[3][c]);
            *(float4*)&dst[base+4] = make_float4(acc[4][c], acc[5][c], acc[6][c], acc[7][c]);
        }
    }
}

// ---------------------------------------------------------------------------
__device__ __forceinline__ void hist_add(unsigned* hist, unsigned bin) {
    unsigned m = __match_any_sync(0xffffffffu, bin);
    if ((int)(threadIdx.x & 31) == __ffs(m) - 1) atomicAdd(&hist[bin], __popc(m));
}

// scores + softmax + pass-1 histogram. 512 threads, 32 rows x 1024 cols.
// Thread covers cols {tx*4..+3} and {512+tx*4..+3} (conflict-free LDS).
__global__ void __launch_bounds__(512, 1) attn_kernel(float* __restrict__ attn) {
    extern __shared__ float sm[];
    float* qs = sm;                        // [64][36] transposed q
    float* ks = sm + 64*36;                // [8][1024]
    float* red = ks + 8*1024;              // [16][8]
    unsigned* hist = (unsigned*)(red + 128);
    int g = blockIdx.y;
    int n0 = blockIdx.x * 32;
    int t = threadIdx.x;
    int tx = t & 127, ty = t >> 7;
    int lane = t & 31, wid = t >> 5;

    for (int i = t; i < 8192; i += 512) hist[i] = 0u;
    {   // load q transposed
        int n = t >> 4, dg = t & 15;
        float4 q4 = *(const float4*)&g_q[((size_t)g * NS + n0 + n) * DH + dg * 4];
        qs[(dg*4+0)*36 + n] = q4.x; qs[(dg*4+1)*36 + n] = q4.y;
        qs[(dg*4+2)*36 + n] = q4.z; qs[(dg*4+3)*36 + n] = q4.w;
    }
    float acc[8][8];
    #pragma unroll
    for (int i = 0; i < 8; i++)
        #pragma unroll
        for (int j = 0; j < 8; j++) acc[i][j] = 0.f;

    for (int dc = 0; dc < 8; dc++) {
        __syncthreads();
        #pragma unroll
        for (int i = 0; i < 4; i++) {
            int idx = t + i * 512;
            int dd = idx >> 8, mg = idx & 255;
            *(float4*)&ks[dd*1024 + mg*4] =
                *(const float4*)&g_k[((size_t)g * DH + dc*8 + dd) * NS + mg*4];
        }
        __syncthreads();
        #pragma unroll
        for (int dd = 0; dd < 8; dd++) {
            int d = dc * 8 + dd;
            float rq[8], ck[8];
            *(float4*)&rq[0] = *(const float4*)&qs[d*36 + ty*8];
            *(float4*)&rq[4] = *(const float4*)&qs[d*36 + ty*8 + 4];
            *(float4*)&ck[0] = *(const float4*)&ks[dd*1024 + tx*4];        // cols tx*4
            *(float4*)&ck[4] = *(const float4*)&ks[dd*1024 + 512 + tx*4];  // cols 512+tx*4
            #pragma unroll
            for (int i = 0; i < 8; i++)
                #pragma unroll
                for (int j = 0; j < 8; j++)
                    acc[i][j] = fmaf(rq[i], ck[j], acc[i][j]);
        }
    }
    // scale + row max (row = n0 + ty*8 + i, owned by 4 warps sharing ty)
    float rmax[8];
    #pragma unroll
    for (int i = 0; i < 8; i++) {
        float m = -1e30f;
        #pragma unroll
        for (int j = 0; j < 8; j++) { acc[i][j] *= 0.125f; m = fmaxf(m, acc[i][j]); }
        #pragma unroll
        for (int off = 16; off >= 1; off >>= 1)
            m = fmaxf(m, __shfl_xor_sync(0xffffffffu, m, off));
        rmax[i] = m;
    }
    __syncthreads();
    if (lane == 0) {
        #pragma unroll
        for (int i = 0; i < 8; i++) red[wid*8 + i] = rmax[i];
    }
    __syncthreads();
    #pragma unroll
    for (int i = 0; i < 8; i++) {
        float m = red[(ty*4)*8 + i];
        m = fmaxf(m, red[(ty*4+1)*8 + i]);
        m = fmaxf(m, red[(ty*4+2)*8 + i]);
        m = fmaxf(m, red[(ty*4+3)*8 + i]);
        rmax[i] = m;
    }
    float rsum[8];
    #pragma unroll
    for (int i = 0; i < 8; i++) {
        float s = 0.f;
        #pragma unroll
        for (int j = 0; j < 8; j++) { acc[i][j] = expf(acc[i][j] - rmax[i]); s += acc[i][j]; }
        #pragma unroll
        for (int off = 16; off >= 1; off >>= 1)
            s += __shfl_xor_sync(0xffffffffu, s, off);
        rsum[i] = s;
    }
    __syncthreads();
    if (lane == 0) {
        #pragma unroll
        for (int i = 0; i < 8; i++) red[wid*8 + i] = rsum[i];
    }
    __syncthreads();
    #pragma unroll
    for (int i = 0; i < 8; i++) {
        float s = red[(ty*4)*8+i] + red[(ty*4+1)*8+i] + red[(ty*4+2)*8+i] + red[(ty*4+3)*8+i];
        rsum[i] = 1.0f / s;
    }
    // write + histogram
    size_t gb = (size_t)g * NN;
    #pragma unroll
    for (int i = 0; i < 8; i++) {
        size_t rowb = gb + (size_t)(n0 + ty*8 + i) * NS;
        float p[8];
        #pragma unroll
        for (int j = 0; j < 8; j++) p[j] = acc[i][j] * rsum[i];
        *(float4*)&attn[rowb + tx*4]       = make_float4(p[0], p[1], p[2], p[3]);
        *(float4*)&attn[rowb + 512 + tx*4] = make_float4(p[4], p[5], p[6], p[7]);
        #pragma unroll
        for (int j = 0; j < 8; j++)
            hist_add(hist, __float_as_uint(p[j]) >> 19);
    }
    __syncthreads();
    for (int i = t; i < 8192; i += 512)
        if (hist[i]) atomicAdd(&g_hist[g*8192 + i], hist[i]);
}

// ---------------------------------------------------------------------------
// scan: find bin holding the krem-th largest, extend prefix, zero hist.
__global__ void scan_kernel() {
    __shared__ unsigned int ssum[256];
    int g = blockIdx.x;
    int t = threadIdx.x;
    unsigned int* h = &g_hist[g * 8192];
    int hi = 8191 - t * 32;
    unsigned int mysum = 0;
    #pragma unroll
    for (int k = 0; k < 32; k++) mysum += h[hi - k];
    ssum[t] = mysum;
    __syncthreads();
    for (int off = 1; off < 256; off <<= 1) {
        unsigned int v = (t >= off) ? ssum[t - off] : 0u;
        __syncthreads();
        ssum[t] += v;
        __syncthreads();
    }
    unsigned int incl = ssum[t], excl = incl - mysum;
    unsigned int kr = g_krem[g];
    if (excl < kr && kr <= incl) {
        unsigned int cum = excl;
        for (int k = 0; k < 32; k++) {
            int bin = hi - k;
            unsigned int c = h[bin];
            if (cum + c >= kr) {
                g_prefix[g] = (g_prefix[g] << 13) | (unsigned long long)bin;
                g_krem[g] = kr - cum;
                break;
            }
            cum += c;
        }
    }
    __syncthreads();
    for (int i = t; i < 8192; i += 256) h[i] = 0u;
}

// ---------------------------------------------------------------------------
// compact candidates matching pass-1 bin; build pass-2 histogram on the fly.
__global__ void compact_kernel(const float* __restrict__ attn) {
    __shared__ unsigned hist[8192];
    int g = blockIdx.y;
    int t = threadIdx.x;
    int lane = t & 31;
    for (int i = t; i < 8192; i += 256) hist[i] = 0u;
    __syncthreads();
    unsigned long long pref = g_prefix[g];
    size_t gb = (size_t)g * NN;
    int base = blockIdx.x * 65536;
    for (int i = t * 4; i < 65536; i += 1024) {
        float4 v4 = *(const float4*)&attn[gb + base + i];
        float vv[4] = {v4.x, v4.y, v4.z, v4.w};
        #pragma unroll
        for (int c = 0; c < 4; c++) {
            int idx = base + i + c;
            unsigned long long key =
                ((unsigned long long)__float_as_uint(vv[c]) << 20) |
                (unsigned long long)(1048575 - idx);
            bool sel = ((key >> 39) == pref);
            unsigned bm = __ballot_sync(0xffffffffu, sel);
            if (bm) {
                int ldr = __ffs(bm) - 1;
                unsigned pos = 0;
                if (lane == ldr) pos = atomicAdd(&g_cnt[g], (unsigned)__popc(bm));
                pos = __shfl_sync(0xffffffffu, pos, ldr);
                if (sel) {
                    g_cand[(size_t)g * CAP + pos + __popc(bm & ((1u << lane) - 1u))] = key;
                    atomicAdd(&hist[(unsigned)((key >> 26) & 8191)], 1u);
                }
            }
        }
    }
    __syncthreads();
    for (int i = t; i < 8192; i += 256)
        if (hist[i]) atomicAdd(&g_hist[g*8192 + i], hist[i]);
}

// passes 3/4 over the compacted list
__global__ void candpass_kernel(int shift) {
    __shared__ unsigned hist[8192];
    int g = blockIdx.y;
    int t = threadIdx.x;
    for (int i = t; i < 8192; i += 256) hist[i] = 0u;
    __syncthreads();
    unsigned long long pref = g_prefix[g];
    unsigned n = g_cnt[g];
    for (unsigned i = blockIdx.x * 256 + t; i < n; i += 8 * 256) {
        unsigned long long key = g_cand[(size_t)g * CAP + i];
        if ((key >> (shift + 13)) == pref)
            atomicAdd(&hist[(unsigned)((key >> shift) & 8191)], 1u);
    }
    __syncthreads();
    for (int i = t; i < 8192; i += 256)
        if (hist[i]) atomicAdd(&g_hist[g*8192 + i], hist[i]);
}

// ---------------------------------------------------------------------------
// AV: 256(n) x 64(d) x 512(m) per block, 8x8 per thread, m split in halves.
// Thread covers d-cols {tx*4..+3} and {32+tx*4..+3} (conflict-free LDS).
__global__ void __launch_bounds__(256) av_kernel(const float* __restrict__ attn) {
    __shared__ float as[32*256];   // [m][n]
    __shared__ float vs[32*64];    // [m][d]
    int g = blockIdx.y;
    int b = g / HEADS, h = g % HEADS;
    int n0 = (blockIdx.x >> 1) * 256;
    int m0 = (blockIdx.x & 1) * 512;
    int t = threadIdx.x;
    int tx = t & 7, ty = t >> 3;
    float acc[8][8];
    #pragma unroll
    for (int i = 0; i < 8; i++)
        #pragma unroll
        for (int j = 0; j < 8; j++) acc[i][j] = 0.f;

    for (int mc = 0; mc < 16; mc++) {
        int mb = m0 + mc * 32;
        __syncthreads();
        {   // attn transpose tile: thread owns row n = t
            const float* src = attn + (size_t)g * NN + (size_t)(n0 + t) * NS + mb;
            #pragma unroll
            for (int i = 0; i < 8; i++) {
                float4 a4 = *(const float4*)&src[i*4];
                as[(i*4+0)*256 + t] = a4.x; as[(i*4+1)*256 + t] = a4.y;
                as[(i*4+2)*256 + t] = a4.z; as[(i*4+3)*256 + t] = a4.w;
            }
        }
        #pragma unroll
        for (int i = 0; i < 2; i++) {
            int idx = t + i * 256;
            int m = idx >> 4, dg = idx & 15;
            *(float4*)&vs[m*64 + dg*4] =
                *(const float4*)&g_v[((size_t)g * NS + mb + m) * DH + dg*4];
        }
        __syncthreads();
        #pragma unroll
        for (int m = 0; m < 32; m++) {
            float ra[8], rv[8];
            *(float4*)&ra[0] = *(const float4*)&as[m*256 + ty*8];
            *(float4*)&ra[4] = *(const float4*)&as[m*256 + ty*8 + 4];
            *(float4*)&rv[0] = *(const float4*)&vs[m*64 + tx*4];       // d tx*4
            *(float4*)&rv[4] = *(const float4*)&vs[m*64 + 32 + tx*4];  // d 32+tx*4
            #pragma unroll
            for (int i = 0; i < 8; i++)
                #pragma unroll
                for (int j = 0; j < 8; j++)
                    acc[i][j] = fmaf(ra[i], rv[j], acc[i][j]);
        }
    }
    float* dst = m0 ? g_oB : g_o;
    #pragma unroll
    for (int j = 0; j < 8; j++) {
        int dcol = (j < 4) ? (tx*4 + j) : (32 + tx*4 + j - 4);
        size_t base = ((size_t)b * CD + h * DH + dcol) * NS + n0 + ty * 8;
        *(float4*)&dst[base]   = make_float4(acc[0][j], acc[1][j], acc[2][j], acc[3][j]);
        *(float4*)&dst[base+4] = make_float4(acc[4][j], acc[5][j], acc[6][j], acc[7][j]);
    }
}

// ---------------------------------------------------------------------------
// out_proj = Wo @ (g_o + g_oB) + bo.  128(o) x 64(n) tiles, 8x4 per thread.
__global__ void __launch_bounds__(256) oproj_kernel(
        const float* __restrict__ Wo, const float* __restrict__ bo,
        float* __restrict__ out) {
    __shared__ float ws[16][128];
    __shared__ float xs[16][64];
    int b = blockIdx.y;
    int otile = (blockIdx.x >> 4) * 128;
    int ntile = (blockIdx.x & 15) * 64;
    int t = threadIdx.x;
    int tx = t & 15, ty = t >> 4;
    float acc[8][4];
    #pragma unroll
    for (int i = 0; i < 8; i++)
        #pragma unroll
        for (int j = 0; j < 4; j++) acc[i][j] = 0.f;

    for (int c0 = 0; c0 < CD; c0 += 16) {
        #pragma unroll
        for (int i = 0; i < 2; i++) {
            int o = t & 127;
            int cg = (t >> 7) + i * 2;
            float4 w4 = *(const float4*)&Wo[(size_t)(otile + o) * CD + c0 + cg * 4];
            ws[cg*4+0][o] = w4.x; ws[cg*4+1][o] = w4.y;
            ws[cg*4+2][o] = w4.z; ws[cg*4+3][o] = w4.w;
        }
        {
            int c = t >> 4, ng = t & 15;
            size_t idx = ((size_t)b * CD + c0 + c) * NS + ntile + ng * 4;
            float4 a = *(const float4*)&g_o[idx];
            float4 bb = *(const float4*)&g_oB[idx];
            xs[c][ng*4+0] = a.x + bb.x; xs[c][ng*4+1] = a.y + bb.y;
            xs[c][ng*4+2] = a.z + bb.z; xs[c][ng*4+3] = a.w + bb.w;
        }
        __syncthreads();
        #pragma unroll
        for (int k = 0; k < 16; k++) {
            float rw[8], rx[4];
            *(float4*)&rw[0] = *(const float4*)&ws[k][ty*8];
            *(float4*)&rw[4] = *(const float4*)&ws[k][ty*8+4];
            *(float4*)&rx[0] = *(const float4*)&xs[k][tx*4];
            #pragma unroll
            for (int i = 0; i < 8; i++)
                #pragma unroll
                for (int j = 0; j < 4; j++)
                    acc[i][j] = fmaf(rw[i], rx[j], acc[i][j]);
        }
        __syncthreads();
    }
    #pragma unroll
    for (int r = 0; r < 8; r++) {
        int o = otile + ty * 8 + r;
        float bias = bo[o];
        *(float4*)&out[((size_t)b * CD + o) * NS + ntile + tx * 4] =
            make_float4(acc[r][0] + bias, acc[r][1] + bias, acc[r][2] + bias, acc[r][3] + bias);
    }
}

// ---------------------------------------------------------------------------
// split into causal / noncausal / mask + attn_map accumulation. float4 IO.
__global__ void mask_kernel(float* __restrict__ out) {
    int g = blockIdx.y;
    int b = g / HEADS;
    unsigned long long thr = g_prefix[g];
    int n0 = blockIdx.x * 16;
    int t = threadIdx.x;
    float* caus = out + OFF_CAUS;
    float* nonc = out + OFF_NONC;
    float* mask = out + OFF_MASK;
    size_t gb = (size_t)g * NN;
    float cs0 = 0.f, cs1 = 0.f, cs2 = 0.f, cs3 = 0.f;
    #pragma unroll 4
    for (int r = 0; r < 16; r++) {
        int idx = (n0 + r) * NS + t * 4;
        float4 v = *(const float4*)&caus[gb + idx];
        float vv[4] = {v.x, v.y, v.z, v.w};
        float cc[4], nc[4], mk[4];
        #pragma unroll
        for (int c = 0; c < 4; c++) {
            unsigned long long key =
                ((unsigned long long)__float_as_uint(vv[c]) << 20) |
                (unsigned long long)(1048575 - (idx + c));
            bool sel = (key >= thr);
            cc[c] = sel ? vv[c] : 0.f;
            nc[c] = sel ? 0.f : vv[c];
            mk[c] = sel ? 1.f : 0.f;
        }
        cs0 += vv[0]; cs1 += vv[1]; cs2 += vv[2]; cs3 += vv[3];
        *(float4*)&caus[gb + idx] = make_float4(cc[0], cc[1], cc[2], cc[3]);
        *(float4*)&nonc[gb + idx] = make_float4(nc[0], nc[1], nc[2], nc[3]);
        *(float4*)&mask[gb + idx] = make_float4(mk[0], mk[1], mk[2], mk[3]);
    }
    const float sc = 1.f / 6144.f;
    atomicAdd(&out[OFF_MAP + b * NS + t*4 + 0], cs0 * sc);
    atomicAdd(&out[OFF_MAP + b * NS + t*4 + 1], cs1 * sc);
    atomicAdd(&out[OFF_MAP + b * NS + t*4 + 2], cs2 * sc);
    atomicAdd(&out[OFF_MAP + b * NS + t*4 + 3], cs3 * sc);
}

// ---------------------------------------------------------------------------
extern "C" void kernel_launch(void* const* d_in, const int* in_sizes, int n_in,
                              void* d_out, int out_size) {
    const float* query   = (const float*)d_in[0];
    const float* context = (const float*)d_in[1];
    const float* Wq      = (const float*)d_in[2];
    const float* Wk      = (const float*)d_in[3];
    const float* Wv      = (const float*)d_in[4];
    const float* Wo      = (const float*)d_in[5];
    const float* bo      = (const float*)d_in[6];
    float* out = (float*)d_out;
    float* attn = out + OFF_CAUS;

    const int ATTN_SMEM = (64*36 + 8*1024 + 128) * 4 + 8192 * 4;
    cudaFuncSetAttribute(attn_kernel, cudaFuncAttributeMaxDynamicSharedMemorySize, ATTN_SMEM);

    initseg_kernel<<<384, 256>>>(out, 0);       // launch 1
    initseg_kernel<<<384, 256>>>(out, 1);       // launch 2
    initseg_kernel<<<16, 256>>>(out, 2);        // launch 3
    initseg_kernel<<<1, 256>>>(out, 3);         // launch 4
    proj_kernel<<<dim3(24, 4, 3), 256>>>(query, context, Wq, Wk, Wv);   // launch 5
    attn_kernel<<<dim3(32, NG), 512, ATTN_SMEM>>>(attn);                // launch 6 (profiled)
    scan_kernel<<<NG, 256>>>();                 // pass 1
    compact_kernel<<<dim3(16, NG), 256>>>(attn);
    scan_kernel<<<NG, 256>>>();                 // pass 2
    candpass_kernel<<<dim3(8, NG), 256>>>(13);
    scan_kernel<<<NG, 256>>>();                 // pass 3
    candpass_kernel<<<dim3(8, NG), 256>>>(0);
    scan_kernel<<<NG, 256>>>();                 // pass 4
    av_kernel<<<dim3(8, NG), 256>>>(attn);
    oproj_kernel<<<dim3(48, 4), 256>>>(Wo, bo, out);
    mask_kernel<<<dim3(64, NG), 256>>>(out);
}